// round 2
// baseline (speedup 1.0000x reference)
#include <cuda_runtime.h>
#include <math.h>

#define NROWS 16384
#define DIN   64
#define HDIM  256
#define LOUT  64
#define NEXP  256
#define TM    64
#define MAXT  (NROWS / TM + NEXP)   // 512 upper bound on tiles

// ---- scratch (no allocations allowed) ----
__device__ int g_cnt[NEXP];
__device__ int g_off[NEXP];
__device__ int g_cur[NEXP];
__device__ int g_sorted[NROWS];
__device__ int g_te[MAXT];
__device__ int g_tr0[MAXT];
__device__ int g_trn[MAXT];

// ---------------- sort/plan kernels ----------------
__global__ void k_prep() { g_cnt[threadIdx.x] = 0; }

__global__ void k_hist(const int* __restrict__ ind) {
    int n = blockIdx.x * blockDim.x + threadIdx.x;
    atomicAdd(&g_cnt[ind[n]], 1);
}

__global__ void k_plan() {
    __shared__ int sc[NEXP];
    int t = threadIdx.x;
    int c = g_cnt[t];
    // inclusive scan of counts
    sc[t] = c; __syncthreads();
    for (int s = 1; s < NEXP; s <<= 1) {
        int v = (t >= s) ? sc[t - s] : 0;
        __syncthreads();
        sc[t] += v;
        __syncthreads();
    }
    int off = sc[t] - c;
    g_off[t] = off;
    g_cur[t] = off;
    int nt = (c + TM - 1) / TM;
    __syncthreads();
    // inclusive scan of tile counts
    sc[t] = nt; __syncthreads();
    for (int s = 1; s < NEXP; s <<= 1) {
        int v = (t >= s) ? sc[t - s] : 0;
        __syncthreads();
        sc[t] += v;
        __syncthreads();
    }
    int tb = sc[t] - nt;
    for (int i = t; i < MAXT; i += NEXP) g_trn[i] = 0;
    __syncthreads();
    for (int j = 0; j < nt; j++) {
        g_te[tb + j]  = t;
        g_tr0[tb + j] = off + j * TM;
        g_trn[tb + j] = min(TM, c - j * TM);
    }
}

__global__ void k_scatter(const int* __restrict__ ind) {
    int n = blockIdx.x * blockDim.x + threadIdx.x;
    int e = ind[n];
    int p = atomicAdd(&g_cur[e], 1);
    g_sorted[p] = n;
}

// ---------------- main MLP kernel ----------------
// One CTA = one (expert, <=64-row) tile. 256 threads.
// smem: Ws (64KB weight slab), H1 (64KB), H2 (64KB), Xs (16KB), rows (256B)
#define SMEM_FLOATS (16384 * 3 + 64 * 64)
#define SMEM_BYTES  (SMEM_FLOATS * 4 + TM * 4)

__global__ __launch_bounds__(256, 1)
void k_mlp(const float* __restrict__ x,
           const float* __restrict__ W1, const float* __restrict__ b1,
           const float* __restrict__ W2, const float* __restrict__ b2,
           const float* __restrict__ Wl, const float* __restrict__ bl,
           float* __restrict__ out)
{
    int bid = blockIdx.x;
    int M = g_trn[bid];
    if (M == 0) return;
    int e  = g_te[bid];
    int r0 = g_tr0[bid];

    extern __shared__ float sm[];
    float* Ws = sm;                 // stage1/2: [k<64][o<256]; stage3: [k<256][o<64]
    float* H1 = sm + 16384;         // [m<64][h<256]
    float* H2 = H1 + 64 * HDIM;     // [m<64][h<256]
    float* Xs = H2 + 64 * HDIM;     // [m<64][k<64]
    int* rows = (int*)(Xs + 64 * DIN);

    int tid = threadIdx.x;

    if (tid < TM)
        rows[tid] = g_sorted[r0 + ((tid < M) ? tid : 0)];
    __syncthreads();

    // ---- load X tile: Xs[m][k] (natural row-major) ----
    for (int idx = tid; idx < TM * (DIN / 4); idx += 256) {
        int m = idx >> 4, ch = idx & 15;
        float4 v = ((const float4*)(x + (size_t)rows[m] * DIN))[ch];
        ((float4*)(Xs + m * DIN))[ch] = v;
    }
    // ---- load W1 slab transposed: Ws[k][o] ----
    {
        int o = tid;
        const float4* base = (const float4*)(W1 + (size_t)e * HDIM * DIN + (size_t)o * DIN);
        #pragma unroll
        for (int c = 0; c < DIN / 4; c++) {
            float4 v = base[c];
            int k = c * 4;
            Ws[(k + 0) * HDIM + o] = v.x;
            Ws[(k + 1) * HDIM + o] = v.y;
            Ws[(k + 2) * HDIM + o] = v.z;
            Ws[(k + 3) * HDIM + o] = v.w;
        }
    }
    __syncthreads();

    int og = tid & 63, mg = tid >> 6;
    int o0 = og * 4, m0 = mg * 16;

    // ---- stage 1: h1 = tanh(W1 @ x + b1) ----
    float a1[4][16];
    #pragma unroll
    for (int i = 0; i < 4; i++)
        #pragma unroll
        for (int j = 0; j < 16; j++) a1[i][j] = 0.f;

    #pragma unroll 2
    for (int k = 0; k < DIN; k++) {
        float4 w = *(const float4*)&Ws[k * HDIM + o0];
        float h[16];
        #pragma unroll
        for (int j = 0; j < 16; j++) h[j] = Xs[(m0 + j) * DIN + k];
        #pragma unroll
        for (int j = 0; j < 16; j++) {
            a1[0][j] += w.x * h[j];
            a1[1][j] += w.y * h[j];
            a1[2][j] += w.z * h[j];
            a1[3][j] += w.w * h[j];
        }
    }
    __syncthreads();   // done reading Ws

    {
        float bb[4];
        #pragma unroll
        for (int i = 0; i < 4; i++) bb[i] = b1[e * HDIM + o0 + i];
        #pragma unroll
        for (int j = 0; j < 16; j++) {
            float4 v;
            v.x = tanhf(a1[0][j] + bb[0]);
            v.y = tanhf(a1[1][j] + bb[1]);
            v.z = tanhf(a1[2][j] + bb[2]);
            v.w = tanhf(a1[3][j] + bb[3]);
            *(float4*)&H1[(m0 + j) * HDIM + o0] = v;
        }
    }
    __syncthreads();

    // ---- stage 2: h2 = tanh(W2 @ h1 + b2), k tiled by 64 ----
    float a2[4][16];
    #pragma unroll
    for (int i = 0; i < 4; i++)
        #pragma unroll
        for (int j = 0; j < 16; j++) a2[i][j] = 0.f;

    for (int kt = 0; kt < HDIM / 64; kt++) {
        {
            int o = tid;
            const float4* base =
                (const float4*)(W2 + (size_t)e * HDIM * HDIM + (size_t)o * HDIM + kt * 64);
            #pragma unroll
            for (int c = 0; c < 16; c++) {
                float4 v = base[c];
                int k = c * 4;
                Ws[(k + 0) * HDIM + o] = v.x;
                Ws[(k + 1) * HDIM + o] = v.y;
                Ws[(k + 2) * HDIM + o] = v.z;
                Ws[(k + 3) * HDIM + o] = v.w;
            }
        }
        __syncthreads();
        #pragma unroll 2
        for (int k = 0; k < 64; k++) {
            float4 w = *(const float4*)&Ws[k * HDIM + o0];
            float h[16];
            #pragma unroll
            for (int j = 0; j < 16; j++) h[j] = H1[(m0 + j) * HDIM + kt * 64 + k];
            #pragma unroll
            for (int j = 0; j < 16; j++) {
                a2[0][j] += w.x * h[j];
                a2[1][j] += w.y * h[j];
                a2[2][j] += w.z * h[j];
                a2[3][j] += w.w * h[j];
            }
        }
        __syncthreads();
    }

    {
        float bb[4];
        #pragma unroll
        for (int i = 0; i < 4; i++) bb[i] = b2[e * HDIM + o0 + i];
        #pragma unroll
        for (int j = 0; j < 16; j++) {
            float4 v;
            v.x = tanhf(a2[0][j] + bb[0]);
            v.y = tanhf(a2[1][j] + bb[1]);
            v.z = tanhf(a2[2][j] + bb[2]);
            v.w = tanhf(a2[3][j] + bb[3]);
            *(float4*)&H2[(m0 + j) * HDIM + o0] = v;
        }
    }

    // ---- load Wl slab transposed: Ws[k<256][o<64] ----
    {
        int o = tid & 63, q = tid >> 6;
        const float4* base =
            (const float4*)(Wl + (size_t)e * LOUT * HDIM + (size_t)o * HDIM + q * 64);
        #pragma unroll
        for (int c = 0; c < 16; c++) {
            float4 v = base[c];
            int k = q * 64 + c * 4;
            Ws[(k + 0) * LOUT + o] = v.x;
            Ws[(k + 1) * LOUT + o] = v.y;
            Ws[(k + 2) * LOUT + o] = v.z;
            Ws[(k + 3) * LOUT + o] = v.w;
        }
    }
    __syncthreads();   // H2 writes + Wl slab visible

    // ---- stage 3: out = Wl @ h2 + bl ----
    {
        int o = og;   // one output column per thread, 16 rows
        float a3[16];
        #pragma unroll
        for (int j = 0; j < 16; j++) a3[j] = 0.f;
        #pragma unroll 2
        for (int k = 0; k < HDIM; k++) {
            float w = Ws[k * LOUT + o];
            #pragma unroll
            for (int j = 0; j < 16; j++)
                a3[j] += w * H2[(m0 + j) * HDIM + k];
        }
        float bo = bl[e * LOUT + o];
        #pragma unroll
        for (int j = 0; j < 16; j++) {
            int m = m0 + j;
            if (m < M)
                out[(size_t)rows[m] * LOUT + o] = a3[j] + bo;
        }
    }
}

// ---------------- launch ----------------
extern "C" void kernel_launch(void* const* d_in, const int* in_sizes, int n_in,
                              void* d_out, int out_size) {
    (void)in_sizes; (void)n_in; (void)out_size;
    const float* x  = (const float*)d_in[0];
    const int*   nd = (const int*)  d_in[1];
    const float* W1 = (const float*)d_in[2];
    const float* b1 = (const float*)d_in[3];
    const float* W2 = (const float*)d_in[4];
    const float* b2 = (const float*)d_in[5];
    const float* Wl = (const float*)d_in[6];
    const float* bl = (const float*)d_in[7];
    float* out = (float*)d_out;

    cudaFuncSetAttribute(k_mlp, cudaFuncAttributeMaxDynamicSharedMemorySize, SMEM_BYTES);

    k_prep<<<1, NEXP>>>();
    k_hist<<<NROWS / 256, 256>>>(nd);
    k_plan<<<1, NEXP>>>();
    k_scatter<<<NROWS / 256, 256>>>(nd);
    k_mlp<<<MAXT, 256, SMEM_BYTES>>>(x, W1, b1, W2, b2, Wl, bl, out);
}